// round 6
// baseline (speedup 1.0000x reference)
#include <cuda_runtime.h>
#include <stdint.h>
#include <math.h>

#define BATCH 128
#define CH 128
#define NN 170
#define TT 12
#define SCALE 0.08838834764831845f  /* 1/sqrt(128) */
#define PAD 172                     /* Ed smem pitch: 16B-aligned rows, conflict-free phases */
#define KROWS 192                   /* k rows padded to 6*32 */

typedef unsigned long long ull;

__device__ float g_xs[BATCH * NN * CH];    /* [b][n][c]  == [21760][128] */
__device__ float g_Ed[BATCH * NN * NN];    /* [b][n][m]  == [21760][170] */
__device__ float g_sum[NN * NN];           /* batch-summed softmax */

/* ---------------- f32x2 helpers ---------------- */
__device__ __forceinline__ uint32_t s2u(const void* p) {
    uint32_t a;
    asm("{ .reg .u64 t; cvta.to.shared.u64 t, %1; cvt.u32.u64 %0, t; }" : "=r"(a) : "l"(p));
    return a;
}
__device__ __forceinline__ void lds_v2(ull& x, ull& y, uint32_t addr) {
    asm("ld.shared.v2.u64 {%0,%1}, [%2];" : "=l"(x), "=l"(y) : "r"(addr));
}
__device__ __forceinline__ ull lds_1(uint32_t addr) {
    ull v; asm("ld.shared.u64 %0, [%1];" : "=l"(v) : "r"(addr)); return v;
}
__device__ __forceinline__ void fma2(ull& d, ull a, ull b) {
    asm("fma.rn.f32x2 %0, %1, %2, %0;" : "+l"(d) : "l"(a), "l"(b));
}
__device__ __forceinline__ ull pack2(float x, float y) {
    ull r; asm("mov.b64 %0, {%1,%2};" : "=l"(r) : "f"(x), "f"(y)); return r;
}
__device__ __forceinline__ float2 unpk(ull v) {
    float2 f; asm("mov.b64 {%0,%1}, %2;" : "=f"(f.x), "=f"(f.y) : "l"(v)); return f;
}

/* ------------------------------------------------------------------ */
/* Kernel 0: zero the batch-sum accumulator                            */
/* ------------------------------------------------------------------ */
__global__ void k_zero() {
    const int i = blockIdx.x * blockDim.x + threadIdx.x;
    if (i < NN * NN) g_sum[i] = 0.f;
}

/* ------------------------------------------------------------------ */
/* Kernel 1: xs[b][n][c] = sum_t x[b][c][n][t]  (reduce T, transpose) */
/* ------------------------------------------------------------------ */
__global__ void k_reduce(const float* __restrict__ x) {
    __shared__ float s[32][NN + 1];
    const int b  = blockIdx.y;
    const int c0 = blockIdx.x * 32;
    const int tid = threadIdx.x;

    for (int i = tid; i < 32 * NN; i += 256) {
        const int c_l = i / NN;
        const int n   = i - c_l * NN;
        const float4* base = (const float4*)(x + ((size_t)((b * CH + c0 + c_l) * NN + n)) * TT);
        float4 v0 = base[0], v1 = base[1], v2 = base[2];
        s[c_l][n] = v0.x + v0.y + v0.z + v0.w
                  + v1.x + v1.y + v1.z + v1.w
                  + v2.x + v2.y + v2.z + v2.w;
    }
    __syncthreads();
    for (int i = tid; i < NN * 32; i += 256) {
        const int n   = i >> 5;
        const int c_l = i & 31;
        g_xs[((size_t)(b * NN + n)) * CH + c0 + c_l] = s[c_l][n];
    }
}

/* ------------------------------------------------------------------ */
/* Kernel 2: Ed = tanh(xs @ E_s), flattened [21760,128]x[128,170]      */
/* grid (3 coltiles, 340 rowtiles), 256 thr, 64x64 tile, 4x4 micro     */
/* f32x2: acc paired over adjacent output columns                      */
/* ------------------------------------------------------------------ */
__global__ void __launch_bounds__(256) k_gemm1(const float* __restrict__ Es) {
    __shared__ float As[16][65];   /* [kk][row] */
    __shared__ float Bs[16][68];   /* [kk][col], pitch 68 -> 16B aligned, conflict-free */

    const int row0 = blockIdx.y * 64;
    const int col0 = blockIdx.x * 64;
    const int tid = threadIdx.x;
    const int tx = tid & 15;
    const int ty = tid >> 4;
    const uint32_t bbase = s2u(&Bs[0][0]);

    ull acc[4][2] = {};   /* [row i][col pair p]; cols (tx*4 .. tx*4+3) */

    for (int kt = 0; kt < CH; kt += 16) {
        for (int l = tid; l < 64 * 16; l += 256) {
            const int r  = l >> 4;
            const int kk = l & 15;
            As[kk][r] = g_xs[(size_t)(row0 + r) * CH + kt + kk];
        }
        for (int l = tid; l < 16 * 64; l += 256) {
            const int kk = l >> 6;
            const int cc = l & 63;
            const int gc = col0 + cc;
            Bs[kk][cc] = (gc < NN) ? Es[(kt + kk) * NN + gc] : 0.f;
        }
        __syncthreads();
#pragma unroll
        for (int kk = 0; kk < 16; kk++) {
            ull b0, b1;
            lds_v2(b0, b1, bbase + (uint32_t)(kk * 68 + tx * 4) * 4u);
#pragma unroll
            for (int i = 0; i < 4; i++) {
                const float a = As[kk][ty * 4 + i];
                const ull a2 = pack2(a, a);
                fma2(acc[i][0], a2, b0);
                fma2(acc[i][1], a2, b1);
            }
        }
        __syncthreads();
    }

#pragma unroll
    for (int i = 0; i < 4; i++) {
        const int gr = row0 + ty * 4 + i;   /* always < 21760 */
        float2 p0 = unpk(acc[i][0]);
        float2 p1 = unpk(acc[i][1]);
        float v[4] = { p0.x, p0.y, p1.x, p1.y };
        float* dst = g_Ed + (size_t)gr * NN;
#pragma unroll
        for (int j = 0; j < 4; j++) {
            const int gc = col0 + tx * 4 + j;
            if (gc < NN) dst[gc] = tanhf(v[j]);
        }
    }
}

/* ------------------------------------------------------------------ */
/* Kernel 3: per batch: relu(Ed Ed^T * SCALE) -> softmax -> atomic sum */
/* grid BATCH, 256 thr, 132KB smem, 6 rows/warp, f32x2 over m          */
/* ------------------------------------------------------------------ */
__global__ void __launch_bounds__(256, 1) k_scores() {
    extern __shared__ float Ed_s[];   /* [KROWS][PAD] */
    const int b    = blockIdx.x;
    const int tid  = threadIdx.x;
    const int warp = tid >> 5;
    const int lane = tid & 31;

    float4 z4 = make_float4(0.f, 0.f, 0.f, 0.f);
    for (int i = tid; i < KROWS * PAD / 4; i += 256)
        ((float4*)Ed_s)[i] = z4;
    __syncthreads();

    const float* Edb = g_Ed + (size_t)b * NN * NN;
    for (int i = tid; i < NN * NN; i += 256) {
        const int r = i / NN;
        const int m = i - r * NN;
        Ed_s[r * PAD + m] = Edb[i];
    }
    __syncthreads();

    const uint32_t sbase = s2u(Ed_s);

    for (int pass = 0; pass < 4; pass++) {
        const int n0 = pass * 48 + warp * 6;
        if (n0 >= NN) continue;   /* warp-uniform */

        ull acc[6][6] = {};       /* [row r][k col j], f32x2 paired over m */

        for (int m = 0; m < 168; m += 4) {
            ull a0[6], a1[6];
#pragma unroll
            for (int r = 0; r < 6; r++)
                lds_v2(a0[r], a1[r], sbase + (uint32_t)((n0 + r) * PAD + m) * 4u);
#pragma unroll
            for (int j = 0; j < 6; j++) {
                const int k = lane + 32 * j;
                ull b0, b1;
                lds_v2(b0, b1, sbase + (uint32_t)(k * PAD + m) * 4u);
#pragma unroll
                for (int r = 0; r < 6; r++) {
                    fma2(acc[r][j], a0[r], b0);
                    fma2(acc[r][j], a1[r], b1);
                }
            }
        }
        /* remainder m = 168,169 (one pair) */
        {
            ull a[6];
#pragma unroll
            for (int r = 0; r < 6; r++)
                a[r] = lds_1(sbase + (uint32_t)((n0 + r) * PAD + 168) * 4u);
#pragma unroll
            for (int j = 0; j < 6; j++) {
                const int k = lane + 32 * j;
                const ull bb = lds_1(sbase + (uint32_t)(k * PAD + 168) * 4u);
#pragma unroll
                for (int r = 0; r < 6; r++)
                    fma2(acc[r][j], a[r], bb);
            }
        }

        /* relu + softmax + atomic mean-accumulate */
#pragma unroll
        for (int r = 0; r < 6; r++) {
            const int n = n0 + r;
            if (n < NN) {        /* warp-uniform */
                float v[6];
                float vmax = 0.f;
#pragma unroll
                for (int j = 0; j < 6; j++) {
                    const int k = lane + 32 * j;
                    if (k < NN) {
                        float2 f = unpk(acc[r][j]);
                        const float sv = (f.x + f.y) * SCALE;
                        v[j] = sv > 0.f ? sv : 0.f;
                        vmax = fmaxf(vmax, v[j]);
                    } else {
                        v[j] = -1.f;
                    }
                }
#pragma unroll
                for (int off = 16; off > 0; off >>= 1)
                    vmax = fmaxf(vmax, __shfl_xor_sync(0xffffffffu, vmax, off));

                float e[6];
                float ssum = 0.f;
#pragma unroll
                for (int j = 0; j < 6; j++) {
                    const int k = lane + 32 * j;
                    if (k < NN) { e[j] = expf(v[j] - vmax); ssum += e[j]; }
                }
#pragma unroll
                for (int off = 16; off > 0; off >>= 1)
                    ssum += __shfl_xor_sync(0xffffffffu, ssum, off);

                const float inv = 1.f / ssum;
                float* dst = g_sum + (size_t)n * NN;
#pragma unroll
                for (int j = 0; j < 6; j++) {
                    const int k = lane + 32 * j;
                    if (k < NN) atomicAdd(dst + k, e[j] * inv);
                }
            }
        }
    }
}

/* ------------------------------------------------------------------ */
/* Kernel 4: threshold the batch sum                                   */
/* ------------------------------------------------------------------ */
__global__ void k_final(float* __restrict__ out) {
    const int i = blockIdx.x * blockDim.x + threadIdx.x;
    if (i >= NN * NN) return;
    out[i] = (g_sum[i] * (1.0f / BATCH) > 0.5f) ? 1.0f : 0.0f;
}

/* ------------------------------------------------------------------ */
extern "C" void kernel_launch(void* const* d_in, const int* in_sizes, int n_in,
                              void* d_out, int out_size) {
    const float* x  = (const float*)d_in[0];
    const float* Es = (const float*)d_in[1];
    float* out = (float*)d_out;

    cudaFuncSetAttribute(k_scores, cudaFuncAttributeMaxDynamicSharedMemorySize,
                         KROWS * PAD * sizeof(float));

    k_zero<<<(NN * NN + 255) / 256, 256>>>();
    k_reduce<<<dim3(4, BATCH), 256>>>(x);
    k_gemm1<<<dim3(3, 340), 256>>>(Es);
    k_scores<<<BATCH, 256, KROWS * PAD * sizeof(float)>>>();
    k_final<<<(NN * NN + 255) / 256, 256>>>(out);
}

// round 7
// speedup vs baseline: 1.4749x; 1.4749x over previous
#include <cuda_runtime.h>
#include <stdint.h>
#include <math.h>

#define BATCH 128
#define CH 128
#define NN 170
#define TT 12
#define SCALE 0.08838834764831845f  /* 1/sqrt(128) */
#define PAD 172                     /* Ed smem pitch */
#define KROWS 192                   /* padded k rows */

typedef unsigned long long ull;

__device__ float g_xs[BATCH * NN * CH];    /* [b][n][c] == [21760][128] */
__device__ float g_Ed[BATCH * NN * NN];    /* [b][n][m] == [21760][170] */
__device__ float g_sum[NN * NN];

/* ---------------- f32x2 helpers ---------------- */
__device__ __forceinline__ uint32_t s2u(const void* p) {
    uint32_t a;
    asm("{ .reg .u64 t; cvta.to.shared.u64 t, %1; cvt.u32.u64 %0, t; }" : "=r"(a) : "l"(p));
    return a;
}
__device__ __forceinline__ void lds_v2(ull& x, ull& y, uint32_t addr) {
    asm("ld.shared.v2.u64 {%0,%1}, [%2];" : "=l"(x), "=l"(y) : "r"(addr));
}
__device__ __forceinline__ void fma2(ull& d, ull a, ull b) {
    asm("fma.rn.f32x2 %0, %1, %2, %0;" : "+l"(d) : "l"(a), "l"(b));
}
__device__ __forceinline__ ull pack2(float x, float y) {
    ull r; asm("mov.b64 %0, {%1,%2};" : "=l"(r) : "f"(x), "f"(y)); return r;
}
__device__ __forceinline__ float2 unpk(ull v) {
    float2 f; asm("mov.b64 {%0,%1}, %2;" : "=f"(f.x), "=f"(f.y) : "l"(v)); return f;
}

/* ------------------------------------------------------------------ */
__global__ void k_zero() {
    const int i = blockIdx.x * blockDim.x + threadIdx.x;
    if (i < NN * NN) g_sum[i] = 0.f;
}

/* ------------------------------------------------------------------ */
/* Kernel 1: xs[b][n][c] = sum_t x[b][c][n][t]                         */
/* ------------------------------------------------------------------ */
__global__ void k_reduce(const float* __restrict__ x) {
    __shared__ float s[32][NN + 1];
    const int b  = blockIdx.y;
    const int c0 = blockIdx.x * 32;
    const int tid = threadIdx.x;

    for (int i = tid; i < 32 * NN; i += 256) {
        const int c_l = i / NN;
        const int n   = i - c_l * NN;
        const float4* base = (const float4*)(x + ((size_t)((b * CH + c0 + c_l) * NN + n)) * TT);
        float4 v0 = base[0], v1 = base[1], v2 = base[2];
        s[c_l][n] = v0.x + v0.y + v0.z + v0.w
                  + v1.x + v1.y + v1.z + v1.w
                  + v2.x + v2.y + v2.z + v2.w;
    }
    __syncthreads();
    for (int i = tid; i < NN * 32; i += 256) {
        const int n   = i >> 5;
        const int c_l = i & 31;
        g_xs[((size_t)(b * NN + n)) * CH + c0 + c_l] = s[c_l][n];
    }
}

/* ------------------------------------------------------------------ */
/* Kernel 2: Ed = tanh(xs @ E_s)  [21760,128]x[128,170]                */
/* grid (2 coltiles, 170 rowtiles), 256 thr, 128x128 tile, 8x8 micro   */
/* ------------------------------------------------------------------ */
__global__ void __launch_bounds__(256) k_gemm1(const float* __restrict__ Es) {
    __shared__ float As[16][132];   /* [kk][row], pitch 132 (528B, 16B-mult) */
    __shared__ float Bs[16][136];   /* [kk][col], pitch 136 (544B, 16B-mult) */

    const int row0 = blockIdx.y * 128;
    const int col0 = blockIdx.x * 128;
    const int tid = threadIdx.x;
    const int tx = tid & 15;        /* cols tx*8 .. tx*8+7 */
    const int ty = tid >> 4;        /* rows ty*8 .. ty*8+7 */
    const uint32_t abase = s2u(&As[0][0]);
    const uint32_t bbase = s2u(&Bs[0][0]);

    ull acc[8][4] = {};             /* [row][col pair] */

    for (int kt = 0; kt < CH; kt += 16) {
        /* As: 128 rows x 16 k, 2 float4 per thread */
#pragma unroll
        for (int p = 0; p < 2; p++) {
            const int l  = tid + p * 256;     /* 0..511 */
            const int r  = l >> 2;
            const int c4 = (l & 3) * 4;
            float4 v = *(const float4*)&g_xs[(size_t)(row0 + r) * CH + kt + c4];
            As[c4 + 0][r] = v.x;
            As[c4 + 1][r] = v.y;
            As[c4 + 2][r] = v.z;
            As[c4 + 3][r] = v.w;
        }
        /* Bs: 16 k x 128 cols, 4 float2 per thread (Es rows only 8B-aligned) */
#pragma unroll
        for (int p = 0; p < 4; p++) {
            const int l  = tid + p * 256;     /* 0..1023 */
            const int kk = l >> 6;
            const int c2 = (l & 63) * 2;
            const int gc = col0 + c2;
            float2 v;
            v.x = (gc     < NN) ? Es[(kt + kk) * NN + gc]     : 0.f;
            v.y = (gc + 1 < NN) ? Es[(kt + kk) * NN + gc + 1] : 0.f;
            *(float2*)&Bs[kk][c2] = v;
        }
        __syncthreads();
#pragma unroll
        for (int kk = 0; kk < 16; kk++) {
            ull ar[4], br[4];
            lds_v2(ar[0], ar[1], abase + (uint32_t)(kk * 132 + ty * 8) * 4u);
            lds_v2(ar[2], ar[3], abase + (uint32_t)(kk * 132 + ty * 8 + 4) * 4u);
            lds_v2(br[0], br[1], bbase + (uint32_t)(kk * 136 + tx * 8) * 4u);
            lds_v2(br[2], br[3], bbase + (uint32_t)(kk * 136 + tx * 8 + 4) * 4u);
#pragma unroll
            for (int h = 0; h < 4; h++) {
                float2 af = unpk(ar[h]);
                const ull a2lo = pack2(af.x, af.x);
                const ull a2hi = pack2(af.y, af.y);
#pragma unroll
                for (int p = 0; p < 4; p++) {
                    fma2(acc[2 * h][p],     a2lo, br[p]);
                    fma2(acc[2 * h + 1][p], a2hi, br[p]);
                }
            }
        }
        __syncthreads();
    }

#pragma unroll
    for (int i = 0; i < 8; i++) {
        const int gr = row0 + ty * 8 + i;   /* rows always < 21760 */
        float* dst = g_Ed + (size_t)gr * NN;
#pragma unroll
        for (int p = 0; p < 4; p++) {
            float2 f = unpk(acc[i][p]);
            const int gc = col0 + tx * 8 + p * 2;
            if (gc     < NN) dst[gc]     = tanhf(f.x);
            if (gc + 1 < NN) dst[gc + 1] = tanhf(f.y);
        }
    }
}

/* ------------------------------------------------------------------ */
/* Kernel 3: relu(Ed Ed^T * SCALE) -> softmax -> atomic batch-sum      */
/* grid 256 (2 CTAs/batch), 512 thr (16 warps x 6 rows), 129KB smem    */
/* ------------------------------------------------------------------ */
__global__ void __launch_bounds__(512, 1) k_scores() {
    extern __shared__ float Ed_s[];   /* [KROWS][PAD] */
    const int bb   = blockIdx.x;
    const int b    = bb >> 1;
    const int half = bb & 1;
    const int n_beg = half * 85;
    const int n_end = n_beg + 85;
    const int tid  = threadIdx.x;
    const int warp = tid >> 5;
    const int lane = tid & 31;

    float4 z4 = make_float4(0.f, 0.f, 0.f, 0.f);
    for (int i = tid; i < KROWS * PAD / 4; i += 512)
        ((float4*)Ed_s)[i] = z4;
    __syncthreads();

    const float* Edb = g_Ed + (size_t)b * NN * NN;
    for (int i = tid; i < NN * NN; i += 512) {
        const int r = i / NN;
        const int m = i - r * NN;
        Ed_s[r * PAD + m] = Edb[i];
    }
    __syncthreads();

    const uint32_t sbase = s2u(Ed_s);
    const int n0 = n_beg + warp * 6;
    if (n0 < n_end) {                 /* warp-uniform */
        ull acc[6][6] = {};           /* [row][k col], f32x2 paired over m */

        /* padded zeros at m=170,171 make the loop exact */
        for (int m = 0; m < PAD; m += 4) {
            ull a0[6], a1[6];
#pragma unroll
            for (int r = 0; r < 6; r++)
                lds_v2(a0[r], a1[r], sbase + (uint32_t)((n0 + r) * PAD + m) * 4u);
#pragma unroll
            for (int j = 0; j < 6; j++) {
                const int k = lane + 32 * j;
                ull b0, b1;
                lds_v2(b0, b1, sbase + (uint32_t)(k * PAD + m) * 4u);
#pragma unroll
                for (int r = 0; r < 6; r++) {
                    fma2(acc[r][j], a0[r], b0);
                    fma2(acc[r][j], a1[r], b1);
                }
            }
        }

#pragma unroll
        for (int r = 0; r < 6; r++) {
            const int n = n0 + r;
            if (n < n_end) {          /* warp-uniform */
                float v[6];
                float vmax = 0.f;
#pragma unroll
                for (int j = 0; j < 6; j++) {
                    const int k = lane + 32 * j;
                    if (k < NN) {
                        float2 f = unpk(acc[r][j]);
                        const float sv = (f.x + f.y) * SCALE;
                        v[j] = sv > 0.f ? sv : 0.f;
                        vmax = fmaxf(vmax, v[j]);
                    } else {
                        v[j] = -1.f;
                    }
                }
#pragma unroll
                for (int off = 16; off > 0; off >>= 1)
                    vmax = fmaxf(vmax, __shfl_xor_sync(0xffffffffu, vmax, off));

                float e[6];
                float ssum = 0.f;
#pragma unroll
                for (int j = 0; j < 6; j++) {
                    const int k = lane + 32 * j;
                    if (k < NN) { e[j] = expf(v[j] - vmax); ssum += e[j]; }
                }
#pragma unroll
                for (int off = 16; off > 0; off >>= 1)
                    ssum += __shfl_xor_sync(0xffffffffu, ssum, off);

                const float inv = 1.f / ssum;
                float* dst = g_sum + (size_t)n * NN;
#pragma unroll
                for (int j = 0; j < 6; j++) {
                    const int k = lane + 32 * j;
                    if (k < NN) atomicAdd(dst + k, e[j] * inv);
                }
            }
        }
    }
}

/* ------------------------------------------------------------------ */
__global__ void k_final(float* __restrict__ out) {
    const int i = blockIdx.x * blockDim.x + threadIdx.x;
    if (i >= NN * NN) return;
    out[i] = (g_sum[i] * (1.0f / BATCH) > 0.5f) ? 1.0f : 0.0f;
}

/* ------------------------------------------------------------------ */
extern "C" void kernel_launch(void* const* d_in, const int* in_sizes, int n_in,
                              void* d_out, int out_size) {
    const float* x  = (const float*)d_in[0];
    const float* Es = (const float*)d_in[1];
    float* out = (float*)d_out;

    cudaFuncSetAttribute(k_scores, cudaFuncAttributeMaxDynamicSharedMemorySize,
                         KROWS * PAD * sizeof(float));

    k_zero<<<(NN * NN + 255) / 256, 256>>>();
    k_reduce<<<dim3(4, BATCH), 256>>>(x);
    k_gemm1<<<dim3(2, 170), 256>>>(Es);
    k_scores<<<2 * BATCH, 512, KROWS * PAD * sizeof(float)>>>();
    k_final<<<(NN * NN + 255) / 256, 256>>>(out);
}